// round 9
// baseline (speedup 1.0000x reference)
#include <cuda_runtime.h>
#include <cuda_fp16.h>
#include <math.h>
#include <stdint.h>

#define BB   64
#define TT   512
#define DD   512
#define UU   1024
#define G4   4096
#define NCTA 128

__device__ float  g_xg[(size_t)BB * TT * G4];                 // [t][b][4096]
__device__ __align__(16) __half g_xh[(size_t)BB * TT * DD];
__device__ __align__(16) __half g_hh[2][BB * UU];
// two independent flat barriers on separate cache lines
__device__ volatile unsigned g_genA; __device__ unsigned g_padA[31];
__device__ unsigned g_cntA;          __device__ unsigned g_padA2[31];
__device__ volatile unsigned g_genB; __device__ unsigned g_padB[31];
__device__ unsigned g_cntB;          __device__ unsigned g_padB2[31];

__device__ __forceinline__ void mma16(float c[4], unsigned a0, unsigned a1,
                                      unsigned a2, unsigned a3,
                                      unsigned b0, unsigned b1) {
    asm volatile(
        "mma.sync.aligned.m16n8k16.row.col.f32.f16.f16.f32 "
        "{%0,%1,%2,%3}, {%4,%5,%6,%7}, {%8,%9}, {%0,%1,%2,%3};"
        : "+f"(c[0]), "+f"(c[1]), "+f"(c[2]), "+f"(c[3])
        : "r"(a0), "r"(a1), "r"(a2), "r"(a3), "r"(b0), "r"(b1));
}
__device__ __forceinline__ uint4 ldsm4(unsigned addr) {
    uint4 r;
    asm volatile("ldmatrix.sync.aligned.m8n8.x4.shared.b16 {%0,%1,%2,%3}, [%4];"
                 : "=r"(r.x), "=r"(r.y), "=r"(r.z), "=r"(r.w) : "r"(addr));
    return r;
}
__device__ __forceinline__ void cp16(unsigned dst, const void* src) {
    asm volatile("cp.async.cg.shared.global [%0], [%1], 16;" :: "r"(dst), "l"(src));
}
__device__ __forceinline__ float sigmoidf_(float x) { return 1.0f / (1.0f + expf(-x)); }
__device__ __forceinline__ unsigned smem_u32(const void* p) {
    unsigned a;
    asm("{ .reg .u64 t; cvta.to.shared.u64 t, %1; cvt.u32.u64 %0, t; }" : "=r"(a) : "l"(p));
    return a;
}
__device__ __forceinline__ int slot_perm(int slot5) {
    int s = slot5 >> 4, p = slot5 & 15;
    int lcp = (p < 8) ? (p >> 1) : ((p - 8) >> 1);
    int add = (p < 8) ? 0 : 2;
    return 8 * lcp + 4 * s + add + (p & 1);
}

// ---- flat barrier, RELATIVE generations only (tid0 calls these) ----
// bar_arrive returns the pre-arrival generation g; release sets gen = g+1.
// bar_poll spins while gen == g. A polling CTA is at most one release behind
// (next release needs its own next arrival), so this can never deadlock.
__device__ __forceinline__ unsigned bar_arrive(volatile unsigned* gen, unsigned* cnt) {
    unsigned g = *gen;
    __threadfence();                                   // release prior writes
    if (atomicAdd(cnt, 1u) == NCTA - 1u) {
        *cnt = 0u;
        __threadfence();
        *gen = g + 1u;
    }
    return g;
}
__device__ __forceinline__ void bar_poll(volatile unsigned* gen, unsigned g) {
    while (*gen == g) { __nanosleep(20); }
    __threadfence();                                   // acquire
}

// ========================== conv_x ==========================
__global__ __launch_bounds__(256) void conv_x(const float* __restrict__ x) {
    const size_t n4 = (size_t)BB * TT * DD / 4;
    for (size_t i = (size_t)blockIdx.x * 256 + threadIdx.x; i < n4;
         i += (size_t)gridDim.x * 256) {
        float4 v = reinterpret_cast<const float4*>(x)[i];
        __half2 h01 = __floats2half2_rn(v.x, v.y);
        __half2 h23 = __floats2half2_rn(v.z, v.w);
        uint2 st;
        st.x = *reinterpret_cast<unsigned*>(&h01);
        st.y = *reinterpret_cast<unsigned*>(&h23);
        reinterpret_cast<uint2*>(g_xh)[i] = st;
    }
}

// ============ xg_kernel: 64 cols per CTA (16 units), grid 512 ============
#define XG_WS 520
#define XG_SMEM (64 * XG_WS * 2)

__global__ __launch_bounds__(256) void xg_kernel(
    const float* __restrict__ Wx, const float* __restrict__ bias)
{
    extern __shared__ __half Wt[];
    const int tid = threadIdx.x, warp = tid >> 5, lane = tid & 31;
    const int lr = lane >> 2, lc = lane & 3;
    const int mo = (warp & 3) * 16, no = (warp >> 2) * 16;
    const int ns = blockIdx.x & 63, mg = blockIdx.x >> 6;
    const int v0 = ns * 16;

    for (int i = tid; i < 64 * 512; i += 256) {
        int n = i & 63, slotg = i >> 6;
        int k = (slotg & ~31) + slot_perm(slotg & 31);
        int col = (n >> 4) * UU + v0 + (n & 15);
        Wt[n * XG_WS + slotg] = __float2half_rn(Wx[(size_t)k * G4 + col]);
    }
    __syncthreads();
    const unsigned WtB = smem_u32(Wt);
    const unsigned bAB = WtB
        + (unsigned)(no + ((lane >> 4) << 3) + (lane & 7)) * (XG_WS * 2)
        + ((lane >> 3) & 1) * 16;

    float bv[2][2][2];
#pragma unroll
    for (int nh = 0; nh < 2; nh++)
#pragma unroll
        for (int j = 0; j < 2; j++) {
            int cl = no + nh * 32 + j * 8 + 2 * lc;
            int colg = (cl >> 4) * UU + v0 + (cl & 15);
            bv[nh][j][0] = bias[colg]; bv[nh][j][1] = bias[colg + 1];
        }

    for (int mt = 0; mt < 64; mt++) {
        const int r0 = mg * 4096 + mt * 64;
        const __half* pr0 = g_xh + (size_t)(r0 + mo + lr) * DD + 8 * lc;
        const __half* pr1 = pr0 + 8 * DD;
        float acc[2][2][4];
#pragma unroll
        for (int nh = 0; nh < 2; nh++)
#pragma unroll
            for (int j = 0; j < 2; j++)
#pragma unroll
                for (int i = 0; i < 4; i++) acc[nh][j][i] = 0.0f;

        uint4 a0c = *reinterpret_cast<const uint4*>(pr0);
        uint4 a1c = *reinterpret_cast<const uint4*>(pr1);
        uint4 a0n = *reinterpret_cast<const uint4*>(pr0 + 32);
        uint4 a1n = *reinterpret_cast<const uint4*>(pr1 + 32);
#pragma unroll
        for (int kc = 0; kc < 16; kc++) {
            uint4 a0f = make_uint4(0, 0, 0, 0), a1f = a0f;
            if (kc < 14) {
                a0f = *reinterpret_cast<const uint4*>(pr0 + (kc + 2) * 32);
                a1f = *reinterpret_cast<const uint4*>(pr1 + (kc + 2) * 32);
            }
#pragma unroll
            for (int nh = 0; nh < 2; nh++) {
                const unsigned ba = bAB + nh * (32 * XG_WS * 2) + kc * 64;
                uint4 B0 = ldsm4(ba);
                uint4 B1 = ldsm4(ba + 32);
                mma16(acc[nh][0], a0c.x, a1c.x, a0c.y, a1c.y, B0.x, B0.y);
                mma16(acc[nh][1], a0c.x, a1c.x, a0c.y, a1c.y, B0.z, B0.w);
                mma16(acc[nh][0], a0c.z, a1c.z, a0c.w, a1c.w, B1.x, B1.y);
                mma16(acc[nh][1], a0c.z, a1c.z, a0c.w, a1c.w, B1.z, B1.w);
            }
            a0c = a0n; a1c = a1n; a0n = a0f; a1n = a1f;
        }
        const int rA = r0 + mo + lr, rB = rA + 8;
        const size_t row0 = (size_t)((rA & (TT - 1)) * BB + (rA >> 9)) * G4;
        const size_t row1 = (size_t)((rB & (TT - 1)) * BB + (rB >> 9)) * G4;
#pragma unroll
        for (int nh = 0; nh < 2; nh++)
#pragma unroll
            for (int j = 0; j < 2; j++) {
                int cl = no + nh * 32 + j * 8 + 2 * lc;
                int colg = (cl >> 4) * UU + v0 + (cl & 15);
                *reinterpret_cast<float2*>(&g_xg[row0 + colg]) =
                    make_float2(acc[nh][j][0] + bv[nh][j][0], acc[nh][j][1] + bv[nh][j][1]);
                *reinterpret_cast<float2*>(&g_xg[row1 + colg]) =
                    make_float2(acc[nh][j][2] + bv[nh][j][0], acc[nh][j][3] + bv[nh][j][1]);
            }
    }
}

// ============== persistent two-stream LSTM step kernel ==============
#define HROW 1032
#define SM_H0 0u
#define SM_H1 66048u
#define SM_W  132096u
#define SM_G0 198144u
#define SM_G1 202368u
#define SM_CL 206592u
#define SMEM_BYTES (206592 + 2048 + 64)

__global__ __launch_bounds__(256) void lstm_persist(
    const float* __restrict__ Wh, const float* __restrict__ h0,
    const float* __restrict__ c0, float* __restrict__ out)
{
    extern __shared__ char sm[];
    const unsigned smB = smem_u32(sm);
    __half* Wt  = (__half*)(sm + SM_W);
    float*  Gk0 = (float*)(sm + SM_G0);
    float*  Gk1 = (float*)(sm + SM_G1);
    float*  Cl  = (float*)(sm + SM_CL);

    const int tid = threadIdx.x, warp = tid >> 5, lane = tid & 31;
    const int lr = lane >> 2, lc = lane & 3;
    const int mo = (warp & 1) * 16;
    const int no = ((warp >> 1) & 1) * 16;
    const int kh = warp >> 2;                        // k-half 0/1
    const int u0 = blockIdx.x * 8;

    // ---- one-time init ----
    for (int i = tid; i < 32 * 1024; i += 256) {
        int n = i & 31, k = i >> 5;
        int col = (n >> 3) * UU + u0 + (n & 7);
        Wt[n * HROW + k] = __float2half_rn(Wh[(size_t)k * G4 + col]);
    }
    for (int i = tid; i < 512; i += 256)
        Cl[i] = c0[(i >> 3) * UU + u0 + (i & 7)];
    for (int i = blockIdx.x * 256 + tid; i < BB * UU; i += NCTA * 256)
        g_hh[0][i] = __float2half_rn(h0[i]);
    __syncthreads();
    if (tid == 0) {                                  // init barrier on A
        unsigned g = bar_arrive(&g_genA, &g_cntA);
        bar_poll(&g_genA, g);
    }
    __syncthreads();

    // ldsm bases (R3-validated patterns, + kh*512 k offset)
    const unsigned aO = (unsigned)((mo + (lane & 15)) * HROW + kh * 512
                                   + (lane >> 4) * 8) * 2u;
    const unsigned bA = smB + SM_W
        + (unsigned)((no + ((lane >> 4) << 3) + (lane & 7)) * HROW + kh * 512
                     + ((lane >> 3) & 1) * 8) * 2u;
    float* GkMine = kh ? Gk1 : Gk0;

    // cp roles: row = tid>>3 (0..31), base seg = tid&7, 16 segs/thread
    const int cprow = tid >> 3, cps0 = tid & 7;

    // cell roles + xg operands for t=0
    const int cm = tid >> 3, cdu = tid & 7;
    float xa[2][4];
#pragma unroll
    for (int g = 0; g < 2; g++) {
        const size_t base = (size_t)(g * 32 + cm) * G4 + u0 + cdu;
        xa[g][0] = g_xg[base];          xa[g][1] = g_xg[base + UU];
        xa[g][2] = g_xg[base + 2 * UU]; xa[g][3] = g_xg[base + 3 * UU];
    }

    // prologue: stage both groups from h[0]
    {
        const __half* hc = g_hh[0];
#pragma unroll
        for (int i = 0; i < 16; i++) {
            int seg = cps0 + 8 * i;
            cp16(smB + SM_H0 + (unsigned)(cprow * HROW + seg * 8) * 2u,
                 hc + (size_t)cprow * UU + seg * 8);
        }
        asm volatile("cp.async.commit_group;");
#pragma unroll
        for (int i = 0; i < 16; i++) {
            int seg = cps0 + 8 * i;
            cp16(smB + SM_H1 + (unsigned)(cprow * HROW + seg * 8) * 2u,
                 hc + (size_t)(32 + cprow) * UU + seg * 8);
        }
        asm volatile("cp.async.commit_group;");
    }

    unsigned gA = 0, gB = 0;     // saved generations (tid0 only)

    for (int t = 0; t < TT; t++) {
        __half* __restrict__ hn = g_hh[(t + 1) & 1];

#pragma unroll 1
        for (int g = 0; g < 2; g++) {
            if (g == 0) asm volatile("cp.async.wait_group 1;");
            else        asm volatile("cp.async.wait_group 0;");
            __syncthreads();

            // gates: m16 x n16 x k512 per warp
            const unsigned aB = smB + (g ? SM_H1 : SM_H0) + aO;
            float acc[2][4];
#pragma unroll
            for (int j = 0; j < 2; j++)
#pragma unroll
                for (int i = 0; i < 4; i++) acc[j][i] = 0.0f;
#pragma unroll 8
            for (int kc = 0; kc < 16; kc++) {
                uint4 A0 = ldsm4(aB + kc * 64);
                uint4 A1 = ldsm4(aB + kc * 64 + 32);
                uint4 B0 = ldsm4(bA + kc * 64);
                uint4 B1 = ldsm4(bA + kc * 64 + 32);
                mma16(acc[0], A0.x, A0.y, A0.z, A0.w, B0.x, B0.y);
                mma16(acc[1], A0.x, A0.y, A0.z, A0.w, B0.z, B0.w);
                mma16(acc[0], A1.x, A1.y, A1.z, A1.w, B1.x, B1.y);
                mma16(acc[1], A1.x, A1.y, A1.z, A1.w, B1.z, B1.w);
            }
#pragma unroll
            for (int j = 0; j < 2; j++) {
                int cl = no + j * 8 + 2 * lc;
                GkMine[(mo + lr) * 33 + cl]         = acc[j][0];
                GkMine[(mo + lr) * 33 + cl + 1]     = acc[j][1];
                GkMine[(mo + lr + 8) * 33 + cl]     = acc[j][2];
                GkMine[(mo + lr + 8) * 33 + cl + 1] = acc[j][3];
            }
            __syncthreads();

            // cell update (1 elem/thread) with free k-half reduction
            {
                float s0 = Gk0[cm * 33 + cdu]      + Gk1[cm * 33 + cdu];
                float s1 = Gk0[cm * 33 + 8 + cdu]  + Gk1[cm * 33 + 8 + cdu];
                float s2 = Gk0[cm * 33 + 16 + cdu] + Gk1[cm * 33 + 16 + cdu];
                float s3 = Gk0[cm * 33 + 24 + cdu] + Gk1[cm * 33 + 24 + cdu];
                float gi = sigmoidf_(s0 + xa[g][0]);
                float gf = sigmoidf_(s1 + xa[g][1]);
                float gg = tanhf    (s2 + xa[g][2]);
                float go = sigmoidf_(s3 + xa[g][3]);
                int e = g * 256 + tid;
                float cv = gf * Cl[e] + gi * gg;
                Cl[e] = cv;
                float hv = go * tanhf(cv);
                hn[(g * 32 + cm) * UU + u0 + cdu] = __float2half_rn(hv);
                if (t == TT - 1) out[(g * 32 + cm) * UU + u0 + cdu] = hv;
            }
            // prefetch xg[t+1] for this group
            if (t + 1 < TT) {
                const size_t base = (size_t)(t + 1) * BB * G4
                                  + (size_t)(g * 32 + cm) * G4 + u0 + cdu;
                xa[g][0] = g_xg[base];          xa[g][1] = g_xg[base + UU];
                xa[g][2] = g_xg[base + 2 * UU]; xa[g][3] = g_xg[base + 3 * UU];
            }
            __threadfence();
            __syncthreads();
            if (tid == 0) {
                if (g == 0) gA = bar_arrive(&g_genA, &g_cntA);
                else        gB = bar_arrive(&g_genB, &g_cntB);
            }
        }

        // restage both groups for t+1 after their releases
        if (t + 1 < TT) {
            const __half* hq = g_hh[(t + 1) & 1];
            if (tid == 0) bar_poll(&g_genA, gA);
            __syncthreads();
#pragma unroll
            for (int i = 0; i < 16; i++) {
                int seg = cps0 + 8 * i;
                cp16(smB + SM_H0 + (unsigned)(cprow * HROW + seg * 8) * 2u,
                     hq + (size_t)cprow * UU + seg * 8);
            }
            asm volatile("cp.async.commit_group;");
            if (tid == 0) bar_poll(&g_genB, gB);
            __syncthreads();
#pragma unroll
            for (int i = 0; i < 16; i++) {
                int seg = cps0 + 8 * i;
                cp16(smB + SM_H1 + (unsigned)(cprow * HROW + seg * 8) * 2u,
                     hq + (size_t)(32 + cprow) * UU + seg * 8);
            }
            asm volatile("cp.async.commit_group;");
        }
    }
}

// ============================================================================
extern "C" void kernel_launch(void* const* d_in, const int* in_sizes, int n_in,
                              void* d_out, int out_size)
{
    const float* x  = (const float*)d_in[0];
    const float* h0 = (const float*)d_in[1];
    const float* c0 = (const float*)d_in[2];
    const float* Wx = (const float*)d_in[3];
    const float* Wh = (const float*)d_in[4];
    const float* b  = (const float*)d_in[5];
    float* out = (float*)d_out;

    conv_x<<<4096, 256>>>(x);

    cudaFuncSetAttribute(xg_kernel, cudaFuncAttributeMaxDynamicSharedMemorySize,
                         XG_SMEM);
    xg_kernel<<<512, 256, XG_SMEM>>>(Wx, b);

    cudaFuncSetAttribute(lstm_persist, cudaFuncAttributeMaxDynamicSharedMemorySize,
                         SMEM_BYTES);
    lstm_persist<<<NCTA, 256, SMEM_BYTES>>>(Wh, h0, c0, out);

    (void)in_sizes; (void)n_in; (void)out_size;
}

// round 10
// speedup vs baseline: 1.2070x; 1.2070x over previous
#include <cuda_runtime.h>
#include <cuda_fp16.h>
#include <math.h>
#include <stdint.h>

#define BB   64
#define TT   512
#define DD   512
#define UU   1024
#define G4   4096
#define NCTA 128

__device__ float  g_xg[(size_t)BB * TT * G4];                 // [t][b][4096]
__device__ __align__(16) __half g_xh[(size_t)BB * TT * DD];
__device__ __align__(16) __half g_hh[2][BB * UU];
__device__ volatile unsigned g_gen; __device__ unsigned g_pad1[31];
__device__ unsigned g_cnt;          __device__ unsigned g_pad2[31];

// ---------------- helpers ---------------------------------------------------
__device__ __forceinline__ void mma16(float c[4], unsigned a0, unsigned a1,
                                      unsigned a2, unsigned a3,
                                      unsigned b0, unsigned b1) {
    asm volatile(
        "mma.sync.aligned.m16n8k16.row.col.f32.f16.f16.f32 "
        "{%0,%1,%2,%3}, {%4,%5,%6,%7}, {%8,%9}, {%0,%1,%2,%3};"
        : "+f"(c[0]), "+f"(c[1]), "+f"(c[2]), "+f"(c[3])
        : "r"(a0), "r"(a1), "r"(a2), "r"(a3), "r"(b0), "r"(b1));
}
__device__ __forceinline__ uint4 ldsm4(unsigned addr) {
    uint4 r;
    asm volatile("ldmatrix.sync.aligned.m8n8.x4.shared.b16 {%0,%1,%2,%3}, [%4];"
                 : "=r"(r.x), "=r"(r.y), "=r"(r.z), "=r"(r.w) : "r"(addr));
    return r;
}
__device__ __forceinline__ void cp16(unsigned dst, const void* src) {
    asm volatile("cp.async.cg.shared.global [%0], [%1], 16;" :: "r"(dst), "l"(src));
}
__device__ __forceinline__ unsigned smem_u32(const void* p) {
    unsigned a;
    asm("{ .reg .u64 t; cvta.to.shared.u64 t, %1; cvt.u32.u64 %0, t; }" : "=r"(a) : "l"(p));
    return a;
}
__device__ __forceinline__ int slot_perm(int slot5) {
    int s = slot5 >> 4, p = slot5 & 15;
    int lcp = (p < 8) ? (p >> 1) : ((p - 8) >> 1);
    int add = (p < 8) ? 0 : 2;
    return 8 * lcp + 4 * s + add + (p & 1);
}
// fast activations: ex2.approx + rcp.approx (rel err ~1e-6)
__device__ __forceinline__ float fsig(float x) {
    float e, r;
    asm("ex2.approx.f32 %0, %1;" : "=f"(e) : "f"(-1.4426950408889634f * x));
    asm("rcp.approx.f32 %0, %1;" : "=f"(r) : "f"(1.0f + e));
    return r;
}
__device__ __forceinline__ float ftanh_(float x) {
    float e, r;
    asm("ex2.approx.f32 %0, %1;" : "=f"(e) : "f"(2.8853900817779268f * x));
    asm("rcp.approx.f32 %0, %1;" : "=f"(r) : "f"(1.0f + e));
    return 1.0f - 2.0f * r;
}
// flat barrier, relative generations (tid0 only)
__device__ __forceinline__ unsigned bar_arrive() {
    unsigned g = g_gen;
    __threadfence();
    if (atomicAdd(&g_cnt, 1u) == NCTA - 1u) {
        g_cnt = 0u;
        __threadfence();
        g_gen = g + 1u;
    }
    return g;
}
__device__ __forceinline__ void bar_poll(unsigned g) {
    while (g_gen == g) { __nanosleep(20); }
    __threadfence();
}

// ========================== conv_x ==========================
__global__ __launch_bounds__(256) void conv_x(const float* __restrict__ x) {
    const size_t n4 = (size_t)BB * TT * DD / 4;
    for (size_t i = (size_t)blockIdx.x * 256 + threadIdx.x; i < n4;
         i += (size_t)gridDim.x * 256) {
        float4 v = reinterpret_cast<const float4*>(x)[i];
        __half2 h01 = __floats2half2_rn(v.x, v.y);
        __half2 h23 = __floats2half2_rn(v.z, v.w);
        uint2 st;
        st.x = *reinterpret_cast<unsigned*>(&h01);
        st.y = *reinterpret_cast<unsigned*>(&h23);
        reinterpret_cast<uint2*>(g_xh)[i] = st;
    }
}

// ================= xg_kernel (R3-validated, 1024 CTAs) =================
#define XG_WT_STRIDE 520
__global__ __launch_bounds__(256) void xg_kernel(
    const float* __restrict__ Wx, const float* __restrict__ bias)
{
    __shared__ __half Wt[32 * XG_WT_STRIDE];
    const int tid = threadIdx.x, warp = tid >> 5, lane = tid & 31;
    const int lr = lane >> 2, lc = lane & 3;
    const int mo = (warp & 3) * 16, no = (warp >> 2) * 16;
    const int ns = blockIdx.x & 127, mg = blockIdx.x >> 7, u0 = ns * 8;

    for (int i = tid; i < 32 * 512; i += 256) {
        int n = i & 31, slotg = i >> 5;
        int k = (slotg & ~31) + slot_perm(slotg & 31);
        int col = (n >> 3) * UU + u0 + (n & 7);
        Wt[n * XG_WT_STRIDE + slotg] = __float2half_rn(Wx[(size_t)k * G4 + col]);
    }
    __syncthreads();
    const unsigned WtB = smem_u32(Wt);
    const unsigned bAddrBase = WtB
        + (unsigned)(no + ((lane >> 4) << 3) + (lane & 7)) * (XG_WT_STRIDE * 2)
        + ((lane >> 3) & 1) * 16;
    float bv[2][2];
#pragma unroll
    for (int j = 0; j < 2; j++) {
        int cl = no + j * 8 + 2 * lc;
        int colg = (cl >> 3) * UU + u0 + (cl & 7);
        bv[j][0] = bias[colg]; bv[j][1] = bias[colg + 1];
    }
    for (int mt = 0; mt < 64; mt++) {
        const int r0 = mg * 4096 + mt * 64;
        const __half* pr0 = g_xh + (size_t)(r0 + mo + lr) * DD + 8 * lc;
        const __half* pr1 = pr0 + 8 * DD;
        float acc[2][4];
#pragma unroll
        for (int j = 0; j < 2; j++)
#pragma unroll
            for (int i = 0; i < 4; i++) acc[j][i] = 0.0f;
        uint4 a0c = *reinterpret_cast<const uint4*>(pr0);
        uint4 a1c = *reinterpret_cast<const uint4*>(pr1);
        uint4 a0n = *reinterpret_cast<const uint4*>(pr0 + 32);
        uint4 a1n = *reinterpret_cast<const uint4*>(pr1 + 32);
#pragma unroll
        for (int kc = 0; kc < 16; kc++) {
            uint4 a0f = make_uint4(0, 0, 0, 0), a1f = a0f;
            if (kc < 14) {
                a0f = *reinterpret_cast<const uint4*>(pr0 + (kc + 2) * 32);
                a1f = *reinterpret_cast<const uint4*>(pr1 + (kc + 2) * 32);
            }
            const unsigned ba = bAddrBase + kc * 64;
            uint4 B0 = ldsm4(ba);
            uint4 B1 = ldsm4(ba + 32);
            mma16(acc[0], a0c.x, a1c.x, a0c.y, a1c.y, B0.x, B0.y);
            mma16(acc[1], a0c.x, a1c.x, a0c.y, a1c.y, B0.z, B0.w);
            mma16(acc[0], a0c.z, a1c.z, a0c.w, a1c.w, B1.x, B1.y);
            mma16(acc[1], a0c.z, a1c.z, a0c.w, a1c.w, B1.z, B1.w);
            a0c = a0n; a1c = a1n; a0n = a0f; a1n = a1f;
        }
        const int rA = r0 + mo + lr, rB = rA + 8;
        const size_t row0 = (size_t)((rA & (TT - 1)) * BB + (rA >> 9)) * G4;
        const size_t row1 = (size_t)((rB & (TT - 1)) * BB + (rB >> 9)) * G4;
#pragma unroll
        for (int j = 0; j < 2; j++) {
            int cl = no + j * 8 + 2 * lc;
            int colg = (cl >> 3) * UU + u0 + (cl & 7);
            *reinterpret_cast<float2*>(&g_xg[row0 + colg]) =
                make_float2(acc[j][0] + bv[j][0], acc[j][1] + bv[j][1]);
            *reinterpret_cast<float2*>(&g_xg[row1 + colg]) =
                make_float2(acc[j][2] + bv[j][0], acc[j][3] + bv[j][1]);
        }
    }
}

// ============== persistent LSTM step kernel (K-split warps) ==============
// Warps: (mo 2) x (no 2) x (kh 2); per warp m32 x n16 x k512.
// Each K-half's 128 threads cp their own h half + named-barrier sync.
#define HROW 1032
#define SM_H  0u
#define SM_W  132096u          // 64*HROW*2
#define SM_G0 198144u          // + 32*HROW*2
#define SM_G1 206592u          // + 64*33*4
#define SM_CL 215040u
#define SMEM_BYTES (215040 + 2048 + 64)

__global__ __launch_bounds__(256) void lstm_persist(
    const float* __restrict__ Wh, const float* __restrict__ h0,
    const float* __restrict__ c0, float* __restrict__ out)
{
    extern __shared__ char sm[];
    const unsigned smB = smem_u32(sm);
    __half* Wt  = (__half*)(sm + SM_W);
    float*  Gk0 = (float*)(sm + SM_G0);
    float*  Gk1 = (float*)(sm + SM_G1);
    float*  Cl  = (float*)(sm + SM_CL);

    const int tid = threadIdx.x, warp = tid >> 5, lane = tid & 31;
    const int lr = lane >> 2, lc = lane & 3;
    const int mo = (warp & 1) * 32;
    const int no = ((warp >> 1) & 1) * 16;
    const int kh = warp >> 2;
    const int u0 = blockIdx.x * 8;

    // ---- one-time init ----
    for (int i = tid; i < 32 * 1024; i += 256) {
        int n = i & 31, k = i >> 5;
        int col = (n >> 3) * UU + u0 + (n & 7);
        Wt[n * HROW + k] = __float2half_rn(Wh[(size_t)k * G4 + col]);
    }
    for (int i = tid; i < 512; i += 256)
        Cl[i] = c0[(i >> 3) * UU + u0 + (i & 7)];
    for (int i = blockIdx.x * 256 + tid; i < BB * UU; i += NCTA * 256)
        g_hh[0][i] = __float2half_rn(h0[i]);
    __syncthreads();
    if (tid == 0) { unsigned g = bar_arrive(); bar_poll(g); }
    __syncthreads();

    // ldsm bases
    const unsigned aB0 = smB + SM_H
        + (unsigned)((mo + (lane & 15)) * HROW + kh * 512 + (lane >> 4) * 8) * 2u;
    const unsigned aB1 = aB0 + 16u * HROW * 2u;
    const unsigned bB = smB + SM_W
        + (unsigned)((no + ((lane >> 4) << 3) + (lane & 7)) * HROW + kh * 512
                     + ((lane >> 3) & 1) * 8) * 2u;
    float* GkMine = kh ? Gk1 : Gk0;

    // cp roles: each K-half's 128 threads stage 64 rows x 512 k of their half
    const int local = tid & 127;
    const int cprow = local >> 1;
    const int kb_cp = kh * 512;                      // == (tid>>7)*512
    const unsigned cpDst0 = smB + SM_H
        + (unsigned)(cprow * HROW + kb_cp + (local & 1) * 8) * 2u;
    const int cpSrcOff = cprow * UU + kb_cp + (local & 1) * 8;

    // cell roles (du pairs) + xg operands for t=0
    const int cm = tid >> 2, cdu = (tid & 3) * 2;
    float2 xa[4];
#pragma unroll
    for (int g = 0; g < 4; g++)
        xa[g] = *reinterpret_cast<const float2*>(
            &g_xg[(size_t)cm * G4 + g * UU + u0 + cdu]);

    unsigned genv = 0;

    for (int t = 0; t < TT; t++) {
        const __half* __restrict__ hc = g_hh[t & 1];
        __half*       __restrict__ hn = g_hh[(t + 1) & 1];

        // ---- stage own k-half (32 x 16B per thread), one commit group ----
        const __half* cpSrc = hc + cpSrcOff;
#pragma unroll
        for (int i = 0; i < 32; i++)
            cp16(cpDst0 + i * 32, cpSrc + i * 16);
        asm volatile("cp.async.commit_group;");

        // preload 8 B frags (step-invariant Wt) during cp flight
        uint4 Bp[8];
#pragma unroll
        for (int i = 0; i < 8; i++) Bp[i] = ldsm4(bB + i * 32);

        asm volatile("cp.async.wait_group 0;");
        asm volatile("bar.sync %0, 128;" :: "r"(1 + kh) : "memory");

        // ---- mma: m32 x n16 x k512 per warp ----
        float acc[2][2][4];
#pragma unroll
        for (int a = 0; a < 2; a++)
#pragma unroll
            for (int b = 0; b < 2; b++)
#pragma unroll
                for (int i = 0; i < 4; i++) acc[a][b][i] = 0.0f;
#pragma unroll
        for (int kc = 0; kc < 32; kc++) {
            uint4 A0 = ldsm4(aB0 + kc * 32);
            uint4 A1 = ldsm4(aB1 + kc * 32);
            uint4 Bv = (kc < 8) ? Bp[kc] : ldsm4(bB + kc * 32);
            mma16(acc[0][0], A0.x, A0.y, A0.z, A0.w, Bv.x, Bv.y);
            mma16(acc[0][1], A0.x, A0.y, A0.z, A0.w, Bv.z, Bv.w);
            mma16(acc[1][0], A1.x, A1.y, A1.z, A1.w, Bv.x, Bv.y);
            mma16(acc[1][1], A1.x, A1.y, A1.z, A1.w, Bv.z, Bv.w);
        }

        // ---- partials by k-half ----
#pragma unroll
        for (int mt = 0; mt < 2; mt++)
#pragma unroll
            for (int j = 0; j < 2; j++) {
                int r0 = mo + mt * 16 + lr;
                int cl = no + j * 8 + 2 * lc;
                GkMine[r0 * 33 + cl]           = acc[mt][j][0];
                GkMine[r0 * 33 + cl + 1]       = acc[mt][j][1];
                GkMine[(r0 + 8) * 33 + cl]     = acc[mt][j][2];
                GkMine[(r0 + 8) * 33 + cl + 1] = acc[mt][j][3];
            }
        __syncthreads();

        // ---- cell update: du pair per thread, free k-half reduction ----
        {
            const int gb = cm * 33 + cdu;
            float s0a = Gk0[gb]      + Gk1[gb],      s0b = Gk0[gb + 1]      + Gk1[gb + 1];
            float s1a = Gk0[gb + 8]  + Gk1[gb + 8],  s1b = Gk0[gb + 9]      + Gk1[gb + 9];
            float s2a = Gk0[gb + 16] + Gk1[gb + 16], s2b = Gk0[gb + 17]     + Gk1[gb + 17];
            float s3a = Gk0[gb + 24] + Gk1[gb + 24], s3b = Gk0[gb + 25]     + Gk1[gb + 25];
            float gi0 = fsig(s0a + xa[0].x), gi1 = fsig(s0b + xa[0].y);
            float gf0 = fsig(s1a + xa[1].x), gf1 = fsig(s1b + xa[1].y);
            float gg0 = ftanh_(s2a + xa[2].x), gg1 = ftanh_(s2b + xa[2].y);
            float go0 = fsig(s3a + xa[3].x), go1 = fsig(s3b + xa[3].y);
            int ce = cm * 8 + cdu;
            float cv0 = gf0 * Cl[ce]     + gi0 * gg0;
            float cv1 = gf1 * Cl[ce + 1] + gi1 * gg1;
            Cl[ce] = cv0; Cl[ce + 1] = cv1;
            float hv0 = go0 * ftanh_(cv0);
            float hv1 = go1 * ftanh_(cv1);
            *reinterpret_cast<__half2*>(&hn[cm * UU + u0 + cdu]) =
                __floats2half2_rn(hv0, hv1);
            if (t == TT - 1)
                *reinterpret_cast<float2*>(&out[cm * UU + u0 + cdu]) =
                    make_float2(hv0, hv1);
        }
        __syncthreads();                         // hn writes done

        // ---- barrier: arrive, prefetch xg[t+1], poll ----
        if (tid == 0) genv = bar_arrive();
        if (t + 1 < TT) {
            const size_t base = (size_t)(t + 1) * BB * G4
                              + (size_t)cm * G4 + u0 + cdu;
#pragma unroll
            for (int g = 0; g < 4; g++)
                xa[g] = *reinterpret_cast<const float2*>(&g_xg[base + g * UU]);
        }
        if (tid == 0) bar_poll(genv);
        __syncthreads();
    }
}

// ============================================================================
extern "C" void kernel_launch(void* const* d_in, const int* in_sizes, int n_in,
                              void* d_out, int out_size)
{
    const float* x  = (const float*)d_in[0];
    const float* h0 = (const float*)d_in[1];
    const float* c0 = (const float*)d_in[2];
    const float* Wx = (const float*)d_in[3];
    const float* Wh = (const float*)d_in[4];
    const float* b  = (const float*)d_in[5];
    float* out = (float*)d_out;

    conv_x<<<4096, 256>>>(x);
    xg_kernel<<<1024, 256>>>(Wx, b);

    cudaFuncSetAttribute(lstm_persist, cudaFuncAttributeMaxDynamicSharedMemorySize,
                         SMEM_BYTES);
    lstm_persist<<<NCTA, 256, SMEM_BYTES>>>(Wh, h0, c0, out);

    (void)in_sizes; (void)n_in; (void)out_size;
}

// round 11
// speedup vs baseline: 1.3977x; 1.1580x over previous
#include <cuda_runtime.h>
#include <cuda_fp16.h>
#include <math.h>
#include <stdint.h>

#define BB   64
#define TT   512
#define DD   512
#define UU   1024
#define G4   4096
#define NCTA 128

__device__ float  g_xg[(size_t)BB * TT * G4];   // [t][b][4096]
__device__ __align__(16) __half g_xh[(size_t)BB * TT * DD];
__device__ __align__(16) __half g_hh[2][BB * UU];
__device__ volatile unsigned g_gen; __device__ unsigned g_pad1[31];
__device__ unsigned g_cnt;          __device__ unsigned g_pad2[31];

// ---------------- helpers ---------------------------------------------------
__device__ __forceinline__ void mma16(float c[4], unsigned a0, unsigned a1,
                                      unsigned a2, unsigned a3,
                                      unsigned b0, unsigned b1) {
    asm volatile(
        "mma.sync.aligned.m16n8k16.row.col.f32.f16.f16.f32 "
        "{%0,%1,%2,%3}, {%4,%5,%6,%7}, {%8,%9}, {%0,%1,%2,%3};"
        : "+f"(c[0]), "+f"(c[1]), "+f"(c[2]), "+f"(c[3])
        : "r"(a0), "r"(a1), "r"(a2), "r"(a3), "r"(b0), "r"(b1));
}
__device__ __forceinline__ uint4 ldsm4(unsigned addr) {
    uint4 r;
    asm volatile("ldmatrix.sync.aligned.m8n8.x4.shared.b16 {%0,%1,%2,%3}, [%4];"
                 : "=r"(r.x), "=r"(r.y), "=r"(r.z), "=r"(r.w) : "r"(addr));
    return r;
}
__device__ __forceinline__ void cp16(unsigned dst, const void* src) {
    asm volatile("cp.async.cg.shared.global [%0], [%1], 16;" :: "r"(dst), "l"(src));
}
__device__ __forceinline__ void cp_commit() {
    asm volatile("cp.async.commit_group;");
}
__device__ __forceinline__ unsigned smem_u32(const void* p) {
    unsigned a;
    asm("{ .reg .u64 t; cvta.to.shared.u64 t, %1; cvt.u32.u64 %0, t; }" : "=r"(a) : "l"(p));
    return a;
}
__device__ __forceinline__ int slot_perm(int slot5) {
    int s = slot5 >> 4, p = slot5 & 15;
    int lcp = (p < 8) ? (p >> 1) : ((p - 8) >> 1);
    int add = (p < 8) ? 0 : 2;
    return 8 * lcp + 4 * s + add + (p & 1);
}
// fast activations (R9-validated): ex2.approx + rcp.approx
__device__ __forceinline__ float fsig(float x) {
    float e, r;
    asm("ex2.approx.f32 %0, %1;" : "=f"(e) : "f"(-1.4426950408889634f * x));
    asm("rcp.approx.f32 %0, %1;" : "=f"(r) : "f"(1.0f + e));
    return r;
}
__device__ __forceinline__ float ftanh_(float x) {
    float e, r;
    asm("ex2.approx.f32 %0, %1;" : "=f"(e) : "f"(2.8853900817779268f * x));
    asm("rcp.approx.f32 %0, %1;" : "=f"(r) : "f"(1.0f + e));
    return 1.0f - 2.0f * r;
}

// ========================== conv_x ==========================
__global__ __launch_bounds__(256) void conv_x(const float* __restrict__ x) {
    const size_t n4 = (size_t)BB * TT * DD / 4;
    for (size_t i = (size_t)blockIdx.x * 256 + threadIdx.x; i < n4;
         i += (size_t)gridDim.x * 256) {
        float4 v = reinterpret_cast<const float4*>(x)[i];
        __half2 h01 = __floats2half2_rn(v.x, v.y);
        __half2 h23 = __floats2half2_rn(v.z, v.w);
        uint2 st;
        st.x = *reinterpret_cast<unsigned*>(&h01);
        st.y = *reinterpret_cast<unsigned*>(&h23);
        reinterpret_cast<uint2*>(g_xh)[i] = st;
    }
}

// ================= xg_kernel (R3-validated) =================
#define XG_WT_STRIDE 520
__global__ __launch_bounds__(256) void xg_kernel(
    const float* __restrict__ Wx, const float* __restrict__ bias)
{
    __shared__ __half Wt[32 * XG_WT_STRIDE];
    const int tid = threadIdx.x, warp = tid >> 5, lane = tid & 31;
    const int lr = lane >> 2, lc = lane & 3;
    const int mo = (warp & 3) * 16, no = (warp >> 2) * 16;
    const int ns = blockIdx.x & 127, mg = blockIdx.x >> 7, u0 = ns * 8;

    for (int i = tid; i < 32 * 512; i += 256) {
        int n = i & 31, slotg = i >> 5;
        int k = (slotg & ~31) + slot_perm(slotg & 31);
        int col = (n >> 3) * UU + u0 + (n & 7);
        Wt[n * XG_WT_STRIDE + slotg] = __float2half_rn(Wx[(size_t)k * G4 + col]);
    }
    __syncthreads();
    const unsigned WtB = smem_u32(Wt);
    const unsigned bAddrBase = WtB
        + (unsigned)(no + ((lane >> 4) << 3) + (lane & 7)) * (XG_WT_STRIDE * 2)
        + ((lane >> 3) & 1) * 16;
    float bv[2][2];
#pragma unroll
    for (int j = 0; j < 2; j++) {
        int cl = no + j * 8 + 2 * lc;
        int colg = (cl >> 3) * UU + u0 + (cl & 7);
        bv[j][0] = bias[colg]; bv[j][1] = bias[colg + 1];
    }
    for (int mt = 0; mt < 64; mt++) {
        const int r0 = mg * 4096 + mt * 64;
        const __half* pr0 = g_xh + (size_t)(r0 + mo + lr) * DD + 8 * lc;
        const __half* pr1 = pr0 + 8 * DD;
        float acc[2][4];
#pragma unroll
        for (int j = 0; j < 2; j++)
#pragma unroll
            for (int i = 0; i < 4; i++) acc[j][i] = 0.0f;
        uint4 a0c = *reinterpret_cast<const uint4*>(pr0);
        uint4 a1c = *reinterpret_cast<const uint4*>(pr1);
        uint4 a0n = *reinterpret_cast<const uint4*>(pr0 + 32);
        uint4 a1n = *reinterpret_cast<const uint4*>(pr1 + 32);
#pragma unroll
        for (int kc = 0; kc < 16; kc++) {
            uint4 a0f = make_uint4(0, 0, 0, 0), a1f = a0f;
            if (kc < 14) {
                a0f = *reinterpret_cast<const uint4*>(pr0 + (kc + 2) * 32);
                a1f = *reinterpret_cast<const uint4*>(pr1 + (kc + 2) * 32);
            }
            const unsigned ba = bAddrBase + kc * 64;
            uint4 B0 = ldsm4(ba);
            uint4 B1 = ldsm4(ba + 32);
            mma16(acc[0], a0c.x, a1c.x, a0c.y, a1c.y, B0.x, B0.y);
            mma16(acc[1], a0c.x, a1c.x, a0c.y, a1c.y, B0.z, B0.w);
            mma16(acc[0], a0c.z, a1c.z, a0c.w, a1c.w, B1.x, B1.y);
            mma16(acc[1], a0c.z, a1c.z, a0c.w, a1c.w, B1.z, B1.w);
            a0c = a0n; a1c = a1n; a0n = a0f; a1n = a1f;
        }
        const int rA = r0 + mo + lr, rB = rA + 8;
        const size_t row0 = (size_t)((rA & (TT - 1)) * BB + (rA >> 9)) * G4;
        const size_t row1 = (size_t)((rB & (TT - 1)) * BB + (rB >> 9)) * G4;
#pragma unroll
        for (int j = 0; j < 2; j++) {
            int cl = no + j * 8 + 2 * lc;
            int colg = (cl >> 3) * UU + u0 + (cl & 7);
            *reinterpret_cast<float2*>(&g_xg[row0 + colg]) =
                make_float2(acc[j][0] + bv[j][0], acc[j][1] + bv[j][1]);
            *reinterpret_cast<float2*>(&g_xg[row1 + colg]) =
                make_float2(acc[j][2] + bv[j][0], acc[j][3] + bv[j][1]);
        }
    }
}

// ============== persistent LSTM step kernel (R3 structure) ==============
#define HS_STRIDE 1032
#define WT_STRIDE 1032
#define WT_BYTES  (32 * WT_STRIDE * 2)
#define HS_BYTES  (64 * HS_STRIDE * 2)
#define SMEM_BYTES (WT_BYTES + HS_BYTES + 64 * 33 * 4 + 512 * 4)

__global__ __launch_bounds__(256) void lstm_persist(
    const float* __restrict__ Wh, const float* __restrict__ h0,
    const float* __restrict__ c0, float* __restrict__ out)
{
    extern __shared__ char smraw[];
    __half* Wt = (__half*)smraw;
    __half* Hs = (__half*)(smraw + WT_BYTES);
    float*  Gs = (float*)(smraw + WT_BYTES + HS_BYTES);
    float*  Cl = Gs + 64 * 33;

    const int tid  = threadIdx.x;
    const int warp = tid >> 5, lane = tid & 31;
    const int lr = lane >> 2, lc = lane & 3;
    const int mo = (warp & 3) * 16;
    const int no = (warp >> 2) * 16;
    const int u0 = blockIdx.x * 8;

    // ---- one-time init ----
    for (int i = tid; i < 32 * 1024; i += 256) {
        int n = i & 31, k = i >> 5;
        int col = (n >> 3) * UU + u0 + (n & 7);
        Wt[n * WT_STRIDE + k] = __float2half_rn(Wh[(size_t)k * G4 + col]);
    }
    for (int i = tid; i < 512; i += 256)
        Cl[i] = c0[(i >> 3) * UU + u0 + (i & 7)];
    for (int i = blockIdx.x * 256 + tid; i < BB * UU; i += NCTA * 256)
        g_hh[0][i] = __float2half_rn(h0[i]);
    __syncthreads();

    if (tid == 0) {                              // initial grid barrier
        unsigned gen = g_gen;
        __threadfence();
        if (atomicAdd(&g_cnt, 1u) == NCTA - 1u) {
            g_cnt = 0; __threadfence(); g_gen = gen + 1;
        } else {
            while (g_gen == gen) { __nanosleep(32); }
        }
        __threadfence();
    }
    __syncthreads();

    const unsigned HsB = smem_u32(Hs);
    const unsigned WtB = smem_u32(Wt);

    const unsigned aBase = HsB
        + (unsigned)((mo + (lane & 15)) * HS_STRIDE + (lane >> 4) * 8) * 2u;
    const unsigned bBase = WtB
        + (unsigned)((no + ((lane >> 4) << 3) + (lane & 7)) * WT_STRIDE
                     + ((lane >> 3) & 1) * 8) * 2u;

    const int cprow = tid >> 2, cpseg = tid & 3;
    const unsigned cpDst = HsB + (unsigned)(cprow * HS_STRIDE + cpseg * 8) * 2u;

    // xv prefetch for t=0 (float2 pairs)
    float2 xv[2][2];
#pragma unroll
    for (int j = 0; j < 2; j++) {
        int cl = no + j * 8 + 2 * lc;
        int colg = (cl >> 3) * UU + u0 + (cl & 7);
        xv[j][0] = *reinterpret_cast<const float2*>(&g_xg[(size_t)(mo + lr) * G4 + colg]);
        xv[j][1] = *reinterpret_cast<const float2*>(&g_xg[(size_t)(mo + lr + 8) * G4 + colg]);
    }

    for (int t = 0; t < TT; t++) {
        const __half* __restrict__ hc = g_hh[t & 1];
        __half*       __restrict__ hn = g_hh[(t + 1) & 1];

        // ---- issue full-h copy (32 commit groups) ----
        const __half* cpSrc = hc + (size_t)cprow * UU + cpseg * 8;
#pragma unroll
        for (int kc = 0; kc < 32; kc++) {
            cp16(cpDst + kc * 64, cpSrc + kc * 32);
            cp_commit();
        }

        // 4 independent accumulator chains: acc[p][j], p = kstep parity
        float acc[2][2][4];
#pragma unroll
        for (int p = 0; p < 2; p++)
#pragma unroll
            for (int j = 0; j < 2; j++)
#pragma unroll
                for (int i = 0; i < 4; i++) acc[p][j][i] = 0.0f;

        // ---- half 1: chunks 0..15 ----
        asm volatile("cp.async.wait_group 16;");
        __syncthreads();
#pragma unroll
        for (int kc = 0; kc < 16; kc++) {
            uint4 A0 = ldsm4(aBase + kc * 64);
            uint4 A1 = ldsm4(aBase + kc * 64 + 32);
            uint4 B0 = ldsm4(bBase + kc * 64);
            uint4 B1 = ldsm4(bBase + kc * 64 + 32);
            mma16(acc[0][0], A0.x, A0.y, A0.z, A0.w, B0.x, B0.y);
            mma16(acc[0][1], A0.x, A0.y, A0.z, A0.w, B0.z, B0.w);
            mma16(acc[1][0], A1.x, A1.y, A1.z, A1.w, B1.x, B1.y);
            mma16(acc[1][1], A1.x, A1.y, A1.z, A1.w, B1.z, B1.w);
        }
        // ---- half 2: chunks 16..31 ----
        asm volatile("cp.async.wait_group 0;");
        __syncthreads();
#pragma unroll
        for (int kc = 16; kc < 32; kc++) {
            uint4 A0 = ldsm4(aBase + kc * 64);
            uint4 A1 = ldsm4(aBase + kc * 64 + 32);
            uint4 B0 = ldsm4(bBase + kc * 64);
            uint4 B1 = ldsm4(bBase + kc * 64 + 32);
            mma16(acc[0][0], A0.x, A0.y, A0.z, A0.w, B0.x, B0.y);
            mma16(acc[0][1], A0.x, A0.y, A0.z, A0.w, B0.z, B0.w);
            mma16(acc[1][0], A1.x, A1.y, A1.z, A1.w, B1.x, B1.y);
            mma16(acc[1][1], A1.x, A1.y, A1.z, A1.w, B1.z, B1.w);
        }

        // ---- epilogue: merge chains + xg into SMEM ----
        const int rA = mo + lr;
#pragma unroll
        for (int j = 0; j < 2; j++) {
            int cl = no + j * 8 + 2 * lc;
            Gs[rA * 33 + cl]           = acc[0][j][0] + acc[1][j][0] + xv[j][0].x;
            Gs[rA * 33 + cl + 1]       = acc[0][j][1] + acc[1][j][1] + xv[j][0].y;
            Gs[(rA + 8) * 33 + cl]     = acc[0][j][2] + acc[1][j][2] + xv[j][1].x;
            Gs[(rA + 8) * 33 + cl + 1] = acc[0][j][3] + acc[1][j][3] + xv[j][1].y;
        }
        __syncthreads();

        // ---- LSTM cell: 2 elems per thread, fast activations ----
#pragma unroll
        for (int q = 0; q < 2; q++) {
            int e  = tid + q * 256;
            int m  = e >> 3, du = e & 7;
            float gi = fsig  (Gs[m * 33 + 0 * 8 + du]);
            float gf = fsig  (Gs[m * 33 + 1 * 8 + du]);
            float gg = ftanh_(Gs[m * 33 + 2 * 8 + du]);
            float go = fsig  (Gs[m * 33 + 3 * 8 + du]);
            float cv = gf * Cl[e] + gi * gg;
            Cl[e] = cv;
            float hv = go * ftanh_(cv);
            hn[m * UU + u0 + du] = __float2half_rn(hv);
            if (t == TT - 1) out[m * UU + u0 + du] = hv;
        }
        __syncthreads();

        // ---- split grid barrier: arrive, prefetch xg[t+1], then wait ----
        unsigned gen;
        if (tid == 0) {
            gen = g_gen;
            __threadfence();
            if (atomicAdd(&g_cnt, 1u) == NCTA - 1u) {
                g_cnt = 0; __threadfence(); g_gen = gen + 1;
            }
        }
        if (t + 1 < TT) {
            const size_t base = (size_t)(t + 1) * BB * G4;
#pragma unroll
            for (int j = 0; j < 2; j++) {
                int cl = no + j * 8 + 2 * lc;
                int colg = (cl >> 3) * UU + u0 + (cl & 7);
                xv[j][0] = *reinterpret_cast<const float2*>(
                    &g_xg[base + (size_t)(mo + lr) * G4 + colg]);
                xv[j][1] = *reinterpret_cast<const float2*>(
                    &g_xg[base + (size_t)(mo + lr + 8) * G4 + colg]);
            }
        }
        if (tid == 0) {
            while (g_gen == gen) { __nanosleep(32); }
            __threadfence();
        }
        __syncthreads();
    }
}

// ============================================================================
extern "C" void kernel_launch(void* const* d_in, const int* in_sizes, int n_in,
                              void* d_out, int out_size)
{
    const float* x  = (const float*)d_in[0];
    const float* h0 = (const float*)d_in[1];
    const float* c0 = (const float*)d_in[2];
    const float* Wx = (const float*)d_in[3];
    const float* Wh = (const float*)d_in[4];
    const float* b  = (const float*)d_in[5];
    float* out = (float*)d_out;

    conv_x<<<4096, 256>>>(x);
    xg_kernel<<<1024, 256>>>(Wx, b);

    cudaFuncSetAttribute(lstm_persist, cudaFuncAttributeMaxDynamicSharedMemorySize,
                         SMEM_BYTES);
    lstm_persist<<<NCTA, 256, SMEM_BYTES>>>(Wh, h0, c0, out);

    (void)in_sizes; (void)n_in; (void)out_size;
}